// round 17
// baseline (speedup 1.0000x reference)
#include <cuda_runtime.h>
#include <cuda_bf16.h>
#include <cstdint>

#define DIN   128
#define DOUT  128
#define MAXN  100000
#define BN_EPS 1e-5f

// dgemm tile: M=64 x N=256, BK=32, double-buffered dynamic SMEM
#define DG_AS_BYTES (2 * 32 * 68 * 4)        // 17408
#define DG_BS_BYTES (2 * 32 * 256 * 4)       // 65536
#define DG_SMEM     (DG_AS_BYTES + DG_BS_BYTES)

// Scratch (allocation-free rule: __device__ globals)
__device__ float g_y1[(size_t)MAXN * DIN];     // Y1 = feat @ W1  [N,128]
__device__ int   g_rowptr[MAXN + 1];
// [0..255]=colsum, [256..511]=colsumsq
__device__ float g_stats[512];

// ---------------------------------------------------------------------------
__device__ __forceinline__ void ffma2(unsigned long long& d,
                                      unsigned long long a,
                                      unsigned long long b) {
    asm("fma.rn.f32x2 %0, %1, %2, %3;" : "=l"(d) : "l"(a), "l"(b), "l"(d));
}
__device__ __forceinline__ unsigned long long pack2(float x) {
    unsigned long long r;
    unsigned int u = __float_as_uint(x);
    asm("mov.b64 %0, {%1, %1};" : "=l"(r) : "r"(u));
    return r;
}
__device__ __forceinline__ float f2lo(unsigned long long x) {
    return __uint_as_float((unsigned int)(x & 0xFFFFFFFFull));
}
__device__ __forceinline__ float f2hi(unsigned long long x) {
    return __uint_as_float((unsigned int)(x >> 32));
}
__device__ __forceinline__ uint32_t smem_u32(const void* p) {
    return (uint32_t)__cvta_generic_to_shared(p);
}
__device__ __forceinline__ void cp16(uint32_t dst, const void* src) {
    asm volatile("cp.async.cg.shared.global [%0], [%1], 16;"
                 :: "r"(dst), "l"(src));
}
#define CP_COMMIT() asm volatile("cp.async.commit_group;" ::: "memory")
#define CP_WAIT1()  asm volatile("cp.async.wait_group 1;" ::: "memory")
#define CP_WAIT0()  asm volatile("cp.async.wait_group 0;" ::: "memory")

// ---------------------------------------------------------------------------
__global__ void zero_stats_kernel() {
    g_stats[threadIdx.x] = 0.0f;          // 512 threads
}

// adj_rows is sorted; scatter row boundaries into CSR row_ptr.
__global__ void build_rowptr_kernel(const int* __restrict__ rows, int E, int N) {
    int e = blockIdx.x * blockDim.x + threadIdx.x;
    if (e >= E) return;
    int r = rows[e];
    int prev = (e == 0) ? -1 : rows[e - 1];
    for (int rr = prev + 1; rr <= r; rr++) g_rowptr[rr] = e;
    if (e == E - 1) {
        for (int rr = r + 1; rr <= N; rr++) g_rowptr[rr] = E;
    }
}

// ---------------------------------------------------------------------------
// Double-GEMM, M=64 x N=256 tile, BK=32, 256 threads, 2 CTAs/SM,
// cp.async double-buffered B, reg-staged A (R15 verified config).
//   p0 = relu(feat@W0)+b0  -> out[:,0:128]  (+ BN column stats)
//   Y1 = feat@W1           -> g_y1          (raw; SpMM consumes it)
__global__ __launch_bounds__(256, 2)
void dgemm_kernel(const float* __restrict__ X,
                  const float* __restrict__ W0,
                  const float* __restrict__ W1,
                  const float* __restrict__ b0,
                  float* __restrict__ out,
                  int N) {
    extern __shared__ __align__(16) char smem_raw[];
    float (*As)[32][68]  = (float (*)[32][68])smem_raw;
    float (*Bs)[32][256] = (float (*)[32][256])(smem_raw + DG_AS_BYTES);
    float (*sred_s)[128] = (float (*)[128])smem_raw;
    float (*sred_q)[128] = (float (*)[128])(smem_raw + 4096);

    int tid = threadIdx.x;
    int tx = tid & 31;                  // lane: 8 cols (4 W0-cols + 4 W1-cols)
    int ty = tid >> 5;                  // warp: 8 rows
    int m0 = blockIdx.x * 64;

    int arow = tid >> 2;                // A-load role: 0..63
    int akq  = (tid & 3) * 4;           // 0,4,8,12
    int agr  = m0 + arow;
    bool avalid = agr < N;
    const float* aptr = X + (size_t)agr * DIN + akq;

    int bq  = tid & 63;                 // B-load role
    int bkr = tid >> 6;                 // 0..3
    int bc4 = bq * 4;
    const float* bw = (bc4 < 128) ? W0 : W1;
    int bcc = (bc4 < 128) ? bc4 : bc4 - 128;

    unsigned long long acc2[4][8];
#pragma unroll
    for (int p = 0; p < 4; p++)
#pragma unroll
        for (int j = 0; j < 8; j++) acc2[p][j] = 0ull;

    // ---- prologue: A(0) direct; B(0), B(1) via cp.async -------------------
    {
        float4 a0 = make_float4(0.f, 0.f, 0.f, 0.f);
        float4 a1 = make_float4(0.f, 0.f, 0.f, 0.f);
        if (avalid) { a0 = *(const float4*)aptr;
                      a1 = *(const float4*)(aptr + 16); }
        As[0][akq + 0][arow] = a0.x;  As[0][akq + 1][arow] = a0.y;
        As[0][akq + 2][arow] = a0.z;  As[0][akq + 3][arow] = a0.w;
        As[0][akq + 16][arow] = a1.x; As[0][akq + 17][arow] = a1.y;
        As[0][akq + 18][arow] = a1.z; As[0][akq + 19][arow] = a1.w;
    }
#pragma unroll
    for (int h = 0; h < 8; h++) {
        int k = bkr + h * 4;
        cp16(smem_u32(&Bs[0][k][bc4]), &bw[(size_t)k * DOUT + bcc]);
    }
    CP_COMMIT();
#pragma unroll
    for (int h = 0; h < 8; h++) {
        int k = bkr + h * 4;
        cp16(smem_u32(&Bs[1][k][bc4]), &bw[(size_t)(32 + k) * DOUT + bcc]);
    }
    CP_COMMIT();

    // ---- pipelined main loop (4 chunks of BK=32) --------------------------
#pragma unroll
    for (int i = 0; i < 4; i++) {
        int b = i & 1;
        if (i < 3) { CP_WAIT1(); } else { CP_WAIT0(); }
        __syncthreads();

        float4 an0 = make_float4(0.f, 0.f, 0.f, 0.f);
        float4 an1 = make_float4(0.f, 0.f, 0.f, 0.f);
        if (i + 1 < 4 && avalid) {
            an0 = *(const float4*)(aptr + (i + 1) * 32);
            an1 = *(const float4*)(aptr + (i + 1) * 32 + 16);
        }

#pragma unroll
        for (int kk = 0; kk < 32; kk++) {
            ulonglong2 a01 = *(const ulonglong2*)&As[b][kk][ty * 8];
            ulonglong2 a23 = *(const ulonglong2*)&As[b][kk][ty * 8 + 4];
            unsigned long long ap[4] = { a01.x, a01.y, a23.x, a23.y };
            float4 bA = *(const float4*)&Bs[b][kk][tx * 4];
            float4 bB = *(const float4*)&Bs[b][kk][128 + tx * 4];
            unsigned long long bd[8] = {
                pack2(bA.x), pack2(bA.y), pack2(bA.z), pack2(bA.w),
                pack2(bB.x), pack2(bB.y), pack2(bB.z), pack2(bB.w)
            };
#pragma unroll
            for (int p = 0; p < 4; p++)
#pragma unroll
                for (int j = 0; j < 8; j++)
                    ffma2(acc2[p][j], ap[p], bd[j]);
        }

        if (i + 1 < 4) {
            As[b ^ 1][akq + 0][arow] = an0.x;  As[b ^ 1][akq + 1][arow] = an0.y;
            As[b ^ 1][akq + 2][arow] = an0.z;  As[b ^ 1][akq + 3][arow] = an0.w;
            As[b ^ 1][akq + 16][arow] = an1.x; As[b ^ 1][akq + 17][arow] = an1.y;
            As[b ^ 1][akq + 18][arow] = an1.z; As[b ^ 1][akq + 19][arow] = an1.w;
        }
        __syncthreads();

        if (i + 2 < 4) {
#pragma unroll
            for (int h = 0; h < 8; h++) {
                int k = bkr + h * 4;
                cp16(smem_u32(&Bs[b][k][bc4]),
                     &bw[(size_t)((i + 2) * 32 + k) * DOUT + bcc]);
            }
            CP_COMMIT();
        }
    }

    // Epilogue (tiles dead; sred aliases them)
    float4 b0v = *(const float4*)&b0[tx * 4];
    float psum[4] = {0.f, 0.f, 0.f, 0.f};
    float psq[4]  = {0.f, 0.f, 0.f, 0.f};

#pragma unroll
    for (int p = 0; p < 4; p++) {
#pragma unroll
        for (int half = 0; half < 2; half++) {
            int m = m0 + ty * 8 + 2 * p + half;
            if (m >= N) continue;
            float v0 = half ? f2hi(acc2[p][0]) : f2lo(acc2[p][0]);
            float v1 = half ? f2hi(acc2[p][1]) : f2lo(acc2[p][1]);
            float v2 = half ? f2hi(acc2[p][2]) : f2lo(acc2[p][2]);
            float v3 = half ? f2hi(acc2[p][3]) : f2lo(acc2[p][3]);
            float r0 = fmaxf(v0, 0.f) + b0v.x;
            float r1 = fmaxf(v1, 0.f) + b0v.y;
            float r2 = fmaxf(v2, 0.f) + b0v.z;
            float r3 = fmaxf(v3, 0.f) + b0v.w;
            *(float4*)&out[(size_t)m * (2 * DOUT) + tx * 4] =
                make_float4(r0, r1, r2, r3);
            psum[0] += r0; psq[0] = fmaf(r0, r0, psq[0]);
            psum[1] += r1; psq[1] = fmaf(r1, r1, psq[1]);
            psum[2] += r2; psq[2] = fmaf(r2, r2, psq[2]);
            psum[3] += r3; psq[3] = fmaf(r3, r3, psq[3]);
            float y0 = half ? f2hi(acc2[p][4]) : f2lo(acc2[p][4]);
            float y1 = half ? f2hi(acc2[p][5]) : f2lo(acc2[p][5]);
            float y2 = half ? f2hi(acc2[p][6]) : f2lo(acc2[p][6]);
            float y3 = half ? f2hi(acc2[p][7]) : f2lo(acc2[p][7]);
            *(float4*)&g_y1[(size_t)m * DIN + tx * 4] =
                make_float4(y0, y1, y2, y3);
        }
    }

    *(float4*)&sred_s[ty][tx * 4] = make_float4(psum[0], psum[1], psum[2], psum[3]);
    *(float4*)&sred_q[ty][tx * 4] = make_float4(psq[0], psq[1], psq[2], psq[3]);
    __syncthreads();
    if (tid < 128) {
        float s = 0.f, q = 0.f;
#pragma unroll
        for (int w = 0; w < 8; w++) { s += sred_s[w][tid]; q += sred_q[w][tid]; }
        atomicAdd(&g_stats[tid], s);
        atomicAdd(&g_stats[256 + tid], q);
    }
}

// ---------------------------------------------------------------------------
// Fused SpMM: p1[n] = relu(sum_e val*Y1[col]) + b1 -> out[:,128:256],
// p1 BN stats fused. TWO rows per warp, edges interleaved across the two
// independent chains -> doubled MLP and averaged row imbalance.
__global__ __launch_bounds__(256)
void spmm_fused_kernel(const float* __restrict__ vals,
                       const int*   __restrict__ cols,
                       const float* __restrict__ b1,
                       float* __restrict__ out,
                       int N) {
    __shared__ float s_sum[128], s_sq[128];
    int tid  = threadIdx.x;
    int lane = tid & 31;
    int gw   = blockIdx.x * 8 + (tid >> 5);   // global warp id
    int r0   = gw * 2;
    int r1   = r0 + 1;
    if (tid < 128) { s_sum[tid] = 0.f; s_sq[tid] = 0.f; }
    __syncthreads();

    if (r0 < N) {
        bool has1 = r1 < N;
        int t0 = g_rowptr[r0], e0 = g_rowptr[r0 + 1];
        int t1 = has1 ? g_rowptr[r1] : 0;
        int e1 = has1 ? g_rowptr[r1 + 1] : 0;

        float4 aA0 = make_float4(0.f, 0.f, 0.f, 0.f);
        float4 aA1 = make_float4(0.f, 0.f, 0.f, 0.f);
        float4 aB0 = make_float4(0.f, 0.f, 0.f, 0.f);
        float4 aB1 = make_float4(0.f, 0.f, 0.f, 0.f);

        // interleaved phase: 2 edges from each row per batch (4 gathers in flight)
        while (t0 + 1 < e0 && t1 + 1 < e1) {
            float v00 = __ldg(&vals[t0]),     v01 = __ldg(&vals[t0 + 1]);
            float v10 = __ldg(&vals[t1]),     v11 = __ldg(&vals[t1 + 1]);
            int c00 = __ldg(&cols[t0]),     c01 = __ldg(&cols[t0 + 1]);
            int c10 = __ldg(&cols[t1]),     c11 = __ldg(&cols[t1 + 1]);
            float4 x00 = __ldg(&((const float4*)&g_y1[(size_t)c00 * DIN])[lane]);
            float4 x01 = __ldg(&((const float4*)&g_y1[(size_t)c01 * DIN])[lane]);
            float4 x10 = __ldg(&((const float4*)&g_y1[(size_t)c10 * DIN])[lane]);
            float4 x11 = __ldg(&((const float4*)&g_y1[(size_t)c11 * DIN])[lane]);
            aA0.x = fmaf(v00, x00.x, aA0.x); aA0.y = fmaf(v00, x00.y, aA0.y);
            aA0.z = fmaf(v00, x00.z, aA0.z); aA0.w = fmaf(v00, x00.w, aA0.w);
            aA1.x = fmaf(v01, x01.x, aA1.x); aA1.y = fmaf(v01, x01.y, aA1.y);
            aA1.z = fmaf(v01, x01.z, aA1.z); aA1.w = fmaf(v01, x01.w, aA1.w);
            aB0.x = fmaf(v10, x10.x, aB0.x); aB0.y = fmaf(v10, x10.y, aB0.y);
            aB0.z = fmaf(v10, x10.z, aB0.z); aB0.w = fmaf(v10, x10.w, aB0.w);
            aB1.x = fmaf(v11, x11.x, aB1.x); aB1.y = fmaf(v11, x11.y, aB1.y);
            aB1.z = fmaf(v11, x11.z, aB1.z); aB1.w = fmaf(v11, x11.w, aB1.w);
            t0 += 2; t1 += 2;
        }
        // drain row0 (4-edge batches then singles)
        for (; t0 + 3 < e0; t0 += 4) {
            float v0 = __ldg(&vals[t0]),     v1 = __ldg(&vals[t0 + 1]);
            float v2 = __ldg(&vals[t0 + 2]), v3 = __ldg(&vals[t0 + 3]);
            int c0 = __ldg(&cols[t0]),     c1 = __ldg(&cols[t0 + 1]);
            int c2 = __ldg(&cols[t0 + 2]), c3 = __ldg(&cols[t0 + 3]);
            float4 x0 = __ldg(&((const float4*)&g_y1[(size_t)c0 * DIN])[lane]);
            float4 x1 = __ldg(&((const float4*)&g_y1[(size_t)c1 * DIN])[lane]);
            float4 x2 = __ldg(&((const float4*)&g_y1[(size_t)c2 * DIN])[lane]);
            float4 x3 = __ldg(&((const float4*)&g_y1[(size_t)c3 * DIN])[lane]);
            aA0.x = fmaf(v0, x0.x, aA0.x); aA0.y = fmaf(v0, x0.y, aA0.y);
            aA0.z = fmaf(v0, x0.z, aA0.z); aA0.w = fmaf(v0, x0.w, aA0.w);
            aA1.x = fmaf(v1, x1.x, aA1.x); aA1.y = fmaf(v1, x1.y, aA1.y);
            aA1.z = fmaf(v1, x1.z, aA1.z); aA1.w = fmaf(v1, x1.w, aA1.w);
            aA0.x = fmaf(v2, x2.x, aA0.x); aA0.y = fmaf(v2, x2.y, aA0.y);
            aA0.z = fmaf(v2, x2.z, aA0.z); aA0.w = fmaf(v2, x2.w, aA0.w);
            aA1.x = fmaf(v3, x3.x, aA1.x); aA1.y = fmaf(v3, x3.y, aA1.y);
            aA1.z = fmaf(v3, x3.z, aA1.z); aA1.w = fmaf(v3, x3.w, aA1.w);
        }
        for (; t0 < e0; t0++) {
            float v = __ldg(&vals[t0]);
            int   c = __ldg(&cols[t0]);
            float4 x = __ldg(&((const float4*)&g_y1[(size_t)c * DIN])[lane]);
            aA0.x = fmaf(v, x.x, aA0.x); aA0.y = fmaf(v, x.y, aA0.y);
            aA0.z = fmaf(v, x.z, aA0.z); aA0.w = fmaf(v, x.w, aA0.w);
        }
        // drain row1
        for (; t1 + 3 < e1; t1 += 4) {
            float v0 = __ldg(&vals[t1]),     v1 = __ldg(&vals[t1 + 1]);
            float v2 = __ldg(&vals[t1 + 2]), v3 = __ldg(&vals[t1 + 3]);
            int c0 = __ldg(&cols[t1]),     c1 = __ldg(&cols[t1 + 1]);
            int c2 = __ldg(&cols[t1 + 2]), c3 = __ldg(&cols[t1 + 3]);
            float4 x0 = __ldg(&((const float4*)&g_y1[(size_t)c0 * DIN])[lane]);
            float4 x1 = __ldg(&((const float4*)&g_y1[(size_t)c1 * DIN])[lane]);
            float4 x2 = __ldg(&((const float4*)&g_y1[(size_t)c2 * DIN])[lane]);
            float4 x3 = __ldg(&((const float4*)&g_y1[(size_t)c3 * DIN])[lane]);
            aB0.x = fmaf(v0, x0.x, aB0.x); aB0.y = fmaf(v0, x0.y, aB0.y);
            aB0.z = fmaf(v0, x0.z, aB0.z); aB0.w = fmaf(v0, x0.w, aB0.w);
            aB1.x = fmaf(v1, x1.x, aB1.x); aB1.y = fmaf(v1, x1.y, aB1.y);
            aB1.z = fmaf(v1, x1.z, aB1.z); aB1.w = fmaf(v1, x1.w, aB1.w);
            aB0.x = fmaf(v2, x2.x, aB0.x); aB0.y = fmaf(v2, x2.y, aB0.y);
            aB0.z = fmaf(v2, x2.z, aB0.z); aB0.w = fmaf(v2, x2.w, aB0.w);
            aB1.x = fmaf(v3, x3.x, aB1.x); aB1.y = fmaf(v3, x3.y, aB1.y);
            aB1.z = fmaf(v3, x3.z, aB1.z); aB1.w = fmaf(v3, x3.w, aB1.w);
        }
        for (; t1 < e1; t1++) {
            float v = __ldg(&vals[t1]);
            int   c = __ldg(&cols[t1]);
            float4 x = __ldg(&((const float4*)&g_y1[(size_t)c * DIN])[lane]);
            aB0.x = fmaf(v, x.x, aB0.x); aB0.y = fmaf(v, x.y, aB0.y);
            aB0.z = fmaf(v, x.z, aB0.z); aB0.w = fmaf(v, x.w, aB0.w);
        }

        float4 bb = __ldg(&((const float4*)b1)[lane]);
        // row0 finalize
        {
            float4 r;
            r.x = fmaxf(aA0.x + aA1.x, 0.f) + bb.x;
            r.y = fmaxf(aA0.y + aA1.y, 0.f) + bb.y;
            r.z = fmaxf(aA0.z + aA1.z, 0.f) + bb.z;
            r.w = fmaxf(aA0.w + aA1.w, 0.f) + bb.w;
            *(float4*)&out[(size_t)r0 * (2 * DOUT) + DOUT + lane * 4] = r;
            atomicAdd(&s_sum[lane * 4 + 0], r.x);
            atomicAdd(&s_sum[lane * 4 + 1], r.y);
            atomicAdd(&s_sum[lane * 4 + 2], r.z);
            atomicAdd(&s_sum[lane * 4 + 3], r.w);
            atomicAdd(&s_sq[lane * 4 + 0], r.x * r.x);
            atomicAdd(&s_sq[lane * 4 + 1], r.y * r.y);
            atomicAdd(&s_sq[lane * 4 + 2], r.z * r.z);
            atomicAdd(&s_sq[lane * 4 + 3], r.w * r.w);
        }
        // row1 finalize
        if (has1) {
            float4 r;
            r.x = fmaxf(aB0.x + aB1.x, 0.f) + bb.x;
            r.y = fmaxf(aB0.y + aB1.y, 0.f) + bb.y;
            r.z = fmaxf(aB0.z + aB1.z, 0.f) + bb.z;
            r.w = fmaxf(aB0.w + aB1.w, 0.f) + bb.w;
            *(float4*)&out[(size_t)r1 * (2 * DOUT) + DOUT + lane * 4] = r;
            atomicAdd(&s_sum[lane * 4 + 0], r.x);
            atomicAdd(&s_sum[lane * 4 + 1], r.y);
            atomicAdd(&s_sum[lane * 4 + 2], r.z);
            atomicAdd(&s_sum[lane * 4 + 3], r.w);
            atomicAdd(&s_sq[lane * 4 + 0], r.x * r.x);
            atomicAdd(&s_sq[lane * 4 + 1], r.y * r.y);
            atomicAdd(&s_sq[lane * 4 + 2], r.z * r.z);
            atomicAdd(&s_sq[lane * 4 + 3], r.w * r.w);
        }
    }
    __syncthreads();
    if (tid < 128) {
        atomicAdd(&g_stats[128 + tid], s_sum[tid]);
        atomicAdd(&g_stats[384 + tid], s_sq[tid]);
    }
}

// ---------------------------------------------------------------------------
// Normalize one 128-col half of out; BN finalize inlined in the prologue.
__global__ __launch_bounds__(256)
void bn_apply_half_kernel(float* __restrict__ out,
                          const float* __restrict__ gamma,
                          const float* __restrict__ beta,
                          int N, int half) {
    __shared__ float scale[128], shift[128];
    int tid = threadIdx.x;
    if (tid < 128) {
        int c = half * 128 + tid;
        float inv_n = 1.0f / (float)N;
        float mean = g_stats[c] * inv_n;
        float var  = g_stats[256 + c] * inv_n - mean * mean;
        float s = __ldg(&gamma[c]) * rsqrtf(var + BN_EPS);
        scale[tid] = s;
        shift[tid] = __ldg(&beta[c]) - mean * s;
    }
    __syncthreads();

    size_t total = (size_t)N * 32;
    size_t i = (size_t)blockIdx.x * blockDim.x + tid;
    size_t stride = (size_t)gridDim.x * blockDim.x;
    const float4* scale4 = (const float4*)scale;
    const float4* shift4 = (const float4*)shift;
    for (; i < total; i += stride) {
        size_t row = i >> 5;
        int    q   = (int)(i & 31);
        float4 s  = scale4[q];
        float4 sh = shift4[q];
        size_t idx = row * 64 + half * 32 + q;
        float4 v = ((float4*)out)[idx];
        v.x = fmaf(v.x, s.x, sh.x);
        v.y = fmaf(v.y, s.y, sh.y);
        v.z = fmaf(v.z, s.z, sh.z);
        v.w = fmaf(v.w, s.w, sh.w);
        ((float4*)out)[idx] = v;
    }
}

// ---------------------------------------------------------------------------
extern "C" void kernel_launch(void* const* d_in, const int* in_sizes, int n_in,
                              void* d_out, int out_size) {
    const float* feat     = (const float*)d_in[0];
    const float* adj_vals = (const float*)d_in[1];
    const float* W0       = (const float*)d_in[2];
    const float* W1       = (const float*)d_in[3];
    const float* b0       = (const float*)d_in[4];
    const float* b1       = (const float*)d_in[5];
    const float* gamma    = (const float*)d_in[6];
    const float* beta     = (const float*)d_in[7];
    const int*   adj_rows = (const int*)d_in[8];
    const int*   adj_cols = (const int*)d_in[9];
    float* out = (float*)d_out;

    int N = in_sizes[0] / DIN;
    int E = in_sizes[1];

    static cudaStream_t s1 = nullptr;
    static cudaEvent_t  eZ = nullptr, eR = nullptr, eD = nullptr, eA0 = nullptr;
    if (s1 == nullptr) {
        cudaStreamCreateWithFlags(&s1, cudaStreamNonBlocking);
        cudaEventCreateWithFlags(&eZ,  cudaEventDisableTiming);
        cudaEventCreateWithFlags(&eR,  cudaEventDisableTiming);
        cudaEventCreateWithFlags(&eD,  cudaEventDisableTiming);
        cudaEventCreateWithFlags(&eA0, cudaEventDisableTiming);
        cudaFuncSetAttribute(dgemm_kernel,
                             cudaFuncAttributeMaxDynamicSharedMemorySize,
                             DG_SMEM);
    }

    int gblocks = (N + 63) / 64;
    int nwarps  = (N + 1) / 2;                       // 2 rows per warp
    int sblocks = (nwarps * 32 + 255) / 256;
    int ablocks = (N * 32 + 255) / 256;
    if (ablocks > 8192) ablocks = 8192;

    // main: zero stats, then FORK
    zero_stats_kernel<<<1, 512>>>();
    cudaEventRecord(eZ, 0);

    // side (forked): rowptr overlaps dgemm
    cudaStreamWaitEvent(s1, eZ, 0);
    build_rowptr_kernel<<<(E + 255) / 256, 256, 0, s1>>>(adj_rows, E, N);
    cudaEventRecord(eR, s1);

    // main: dgemm (BK=32, dynamic smem)
    dgemm_kernel<<<gblocks, 256, DG_SMEM>>>(feat, W0, W1, b0, out, N);
    cudaEventRecord(eD, 0);

    // side: p0's BN half (finalize inlined) runs during spmm
    cudaStreamWaitEvent(s1, eD, 0);
    bn_apply_half_kernel<<<ablocks, 256, 0, s1>>>(out, gamma, beta, N, 0);
    cudaEventRecord(eA0, s1);

    // main: spmm (needs rowptr + Y1; stats fused) -> p1 BN half
    cudaStreamWaitEvent(0, eR, 0);
    spmm_fused_kernel<<<sblocks, 256>>>(adj_vals, adj_cols, b1, out, N);
    bn_apply_half_kernel<<<ablocks, 256>>>(out, gamma, beta, N, 1);

    // join side branch before capture ends
    cudaStreamWaitEvent(0, eA0, 0);
}